// round 1
// baseline (speedup 1.0000x reference)
#include <cuda_runtime.h>
#include <math.h>

#define C_CELLS 128
#define H_DIM   256
#define CE_DIM  64
#define MAXG    2048

// scratch (allocation-free rule: __device__ globals)
__device__ float g_hidden[C_CELLS * H_DIM];   // elu(ctrl@ce_w1+b1)
__device__ float g_Abuf[C_CELLS * H_DIM];     // ce @ W1[1:65]
__device__ float g_Bbuf[MAXG * H_DIM];        // ge@W1[65:129] + shift*W1[129] + 128*W1[130] + b1

__device__ __forceinline__ float eluf(float x) {
    return x > 0.f ? x : (__expf(x) - 1.f);
}

// ---------------------------------------------------------------------------
// K1: hidden[c,h] = elu( sum_k ctrl[c,k]*ce_w1[k,h] + ce_b1[h] )
// grid: C_CELLS blocks x H_DIM threads, dynamic smem = G floats
// ---------------------------------------------------------------------------
__global__ void k_hidden(const float* __restrict__ ctrl,
                         const float* __restrict__ w,   // [G, 256]
                         const float* __restrict__ b,   // [256]
                         int G) {
    extern __shared__ float s[];
    int c = blockIdx.x, t = threadIdx.x;
    for (int k = t; k < G; k += blockDim.x) s[k] = ctrl[c * G + k];
    __syncthreads();
    float a0 = 0.f, a1 = 0.f, a2 = 0.f, a3 = 0.f;
    int k = 0;
    for (; k + 3 < G; k += 4) {
        a0 = fmaf(s[k+0], w[(k+0) * H_DIM + t], a0);
        a1 = fmaf(s[k+1], w[(k+1) * H_DIM + t], a1);
        a2 = fmaf(s[k+2], w[(k+2) * H_DIM + t], a2);
        a3 = fmaf(s[k+3], w[(k+3) * H_DIM + t], a3);
    }
    for (; k < G; k++) a0 = fmaf(s[k], w[k * H_DIM + t], a0);
    float acc = (a0 + a1) + (a2 + a3) + b[t];
    g_hidden[c * H_DIM + t] = eluf(acc);
}

// ---------------------------------------------------------------------------
// K2: ce[c,:] = hidden[c,:] @ ce_w2 + ce_b2  (64)  then  A[c,:] = ce[c,:] @ W1[1:65,:]
// grid: C_CELLS blocks x 256 threads
// ---------------------------------------------------------------------------
__global__ void k_ceA(const float* __restrict__ ce_w2,  // [256,64]
                      const float* __restrict__ ce_b2,  // [64]
                      const float* __restrict__ gw1) {  // [131,256]
    __shared__ float s_hid[H_DIM];
    __shared__ float s_ce[CE_DIM];
    int c = blockIdx.x, t = threadIdx.x;
    s_hid[t] = g_hidden[c * H_DIM + t];
    __syncthreads();
    if (t < CE_DIM) {
        float a = ce_b2[t];
        #pragma unroll 4
        for (int k = 0; k < H_DIM; k++) a = fmaf(s_hid[k], ce_w2[k * CE_DIM + t], a);
        s_ce[t] = a;
    }
    __syncthreads();
    float a = 0.f;
    #pragma unroll
    for (int j = 0; j < CE_DIM; j++) a = fmaf(s_ce[j], gw1[(1 + j) * H_DIM + t], a);
    g_Abuf[c * H_DIM + t] = a;
}

// ---------------------------------------------------------------------------
// K3: B[g,:] = ge[gi,:] @ W1[65:129,:] + shift[gi]*W1[129,:] + C*W1[130,:] + g_b1
// grid: G blocks x 256 threads
// ---------------------------------------------------------------------------
__global__ void k_B(const float* __restrict__ gene_table, // [Gtab,64]
                    const float* __restrict__ shift_vec,
                    const int*   __restrict__ gidx,
                    const float* __restrict__ gw1,         // [131,256]
                    const float* __restrict__ gb1) {
    __shared__ float s_ge[CE_DIM];
    __shared__ float s_shift;
    int g = blockIdx.x, t = threadIdx.x;
    int gi = gidx[g];
    if (t < CE_DIM) s_ge[t] = gene_table[gi * CE_DIM + t];
    if (t == 0) s_shift = shift_vec[gi];
    __syncthreads();
    float a = gb1[t]
            + s_shift * gw1[129 * H_DIM + t]
            + (float)C_CELLS * gw1[130 * H_DIM + t];
    #pragma unroll
    for (int j = 0; j < CE_DIM; j++) a = fmaf(s_ge[j], gw1[(65 + j) * H_DIM + t], a);
    g_Bbuf[g * H_DIM + t] = a;
}

// ---------------------------------------------------------------------------
// K4 main: per-gene fused layer1 -> mean -> r -> GEMM(h1@W2a) -> elu*w3a -> softmax
// grid: G blocks x 512 threads, dynamic smem
// ---------------------------------------------------------------------------
__global__ void __launch_bounds__(512, 1)
k_main(const float* __restrict__ ctrl,    // [128, Gc]
       const int*   __restrict__ gidx,
       const float* __restrict__ gw1,     // [131,256] (row 0 = ctrl coeff)
       const float* __restrict__ gw2,     // [512,256] (rows 0..255 = W2a, 256..511 = W2b)
       const float* __restrict__ gb2,     // [256]
       const float* __restrict__ gw3,     // [512] (first 256 = w3a)
       float*       __restrict__ out,     // [128, G]
       int G, int Gc) {
    extern __shared__ float sm[];
    float* s_h1    = sm;             // 128*256
    float* s_ctrlg = s_h1 + 32768;   // 128
    float* s_w10   = s_ctrlg + 128;  // 256
    float* s_Brow  = s_w10 + 256;    // 256
    float* s_p1    = s_Brow + 256;   // 256
    float* s_r     = s_p1 + 256;     // 256
    float* s_w3a   = s_r + 256;      // 256
    float* s_logit = s_w3a + 256;    // 128
    float* s_red   = s_logit + 128;  // 32

    const int g = blockIdx.x;
    const int t = threadIdx.x;
    const int gi = gidx[g];

    if (t < 128) { s_ctrlg[t] = ctrl[t * Gc + gi]; s_logit[t] = 0.f; }
    if (t < 256) { s_w10[t] = gw1[t]; s_w3a[t] = gw3[t]; }
    else         { int u = t - 256; s_Brow[u] = g_Bbuf[g * H_DIM + u]; }
    __syncthreads();

    // pass 1: h1[c,h] = elu(ctrl[c,gi]*W1[0,h] + A[c,h] + B[g,h])
    for (int i = t; i < C_CELLS * H_DIM; i += 512) {
        int c = i >> 8, h = i & 255;
        float v = fmaf(s_ctrlg[c], s_w10[h], g_Abuf[i] + s_Brow[h]);
        s_h1[i] = eluf(v);
    }
    __syncthreads();

    // p1[h] = mean_c h1[c,h]
    if (t < 256) {
        float a0 = 0.f, a1 = 0.f, a2 = 0.f, a3 = 0.f;
        #pragma unroll 4
        for (int c = 0; c < C_CELLS; c += 4) {
            a0 += s_h1[(c + 0) * H_DIM + t];
            a1 += s_h1[(c + 1) * H_DIM + t];
            a2 += s_h1[(c + 2) * H_DIM + t];
            a3 += s_h1[(c + 3) * H_DIM + t];
        }
        s_p1[t] = ((a0 + a1) + (a2 + a3)) * (1.f / (float)C_CELLS);
    }
    __syncthreads();

    // r[h'] = p1 @ W2b + b2
    if (t < 256) {
        const float* w2b = gw2 + 256 * H_DIM;
        float a0 = gb2[t], a1 = 0.f, a2 = 0.f, a3 = 0.f;
        #pragma unroll 4
        for (int h = 0; h < H_DIM; h += 4) {
            a0 = fmaf(s_p1[h + 0], w2b[(h + 0) * H_DIM + t], a0);
            a1 = fmaf(s_p1[h + 1], w2b[(h + 1) * H_DIM + t], a1);
            a2 = fmaf(s_p1[h + 2], w2b[(h + 2) * H_DIM + t], a2);
            a3 = fmaf(s_p1[h + 3], w2b[(h + 3) * H_DIM + t], a3);
        }
        s_r[t] = (a0 + a1) + (a2 + a3);
    }
    __syncthreads();

    // GEMM: x2[c,col] = h1[c,:] @ W2a[:,col];  logit[c] += elu(x2+r[col])*w3a[col]
    {
        const int col  = t & (H_DIM - 1);
        const int half = t >> 8;            // 0 or 1
        const float rcol = s_r[col];
        const float wc   = s_w3a[col];
        const int lane = t & 31;

        for (int chunk = 0; chunk < 8; chunk++) {
            const int cbase = chunk * 16 + half * 8;
            float acc[8];
            #pragma unroll
            for (int ci = 0; ci < 8; ci++) acc[ci] = 0.f;

            #pragma unroll 2
            for (int h = 0; h < H_DIM; h += 4) {
                float w0 = gw2[(h + 0) * H_DIM + col];
                float w1 = gw2[(h + 1) * H_DIM + col];
                float w2 = gw2[(h + 2) * H_DIM + col];
                float w3 = gw2[(h + 3) * H_DIM + col];
                #pragma unroll
                for (int ci = 0; ci < 8; ci++) {
                    const float4 a = *reinterpret_cast<const float4*>(
                        &s_h1[(cbase + ci) * H_DIM + h]);
                    acc[ci] = fmaf(a.x, w0, acc[ci]);
                    acc[ci] = fmaf(a.y, w1, acc[ci]);
                    acc[ci] = fmaf(a.z, w2, acc[ci]);
                    acc[ci] = fmaf(a.w, w3, acc[ci]);
                }
            }
            #pragma unroll
            for (int ci = 0; ci < 8; ci++) {
                float v = eluf(acc[ci] + rcol) * wc;
                #pragma unroll
                for (int off = 16; off; off >>= 1)
                    v += __shfl_down_sync(0xffffffffu, v, off);
                if (lane == 0) atomicAdd(&s_logit[cbase + ci], v);
            }
        }
    }
    __syncthreads();

    // softmax over 128 cells (per-gene constants cancelled analytically)
    {
        const int lane = t & 31;
        const int wid  = t >> 5;
        float l = (t < 128) ? s_logit[t] : -1e30f;
        float m = l;
        #pragma unroll
        for (int off = 16; off; off >>= 1)
            m = fmaxf(m, __shfl_xor_sync(0xffffffffu, m, off));
        if (lane == 0) s_red[wid] = m;
        __syncthreads();
        if (t < 32) {
            float mm = (t < 16) ? s_red[t] : -1e30f;
            #pragma unroll
            for (int off = 8; off; off >>= 1)
                mm = fmaxf(mm, __shfl_xor_sync(0xffffffffu, mm, off));
            if (t == 0) s_red[16] = mm;
        }
        __syncthreads();
        const float M = s_red[16];
        float e = (t < 128) ? __expf(l - M) : 0.f;
        float s = e;
        #pragma unroll
        for (int off = 16; off; off >>= 1)
            s += __shfl_xor_sync(0xffffffffu, s, off);
        if (lane == 0) s_red[wid] = s;
        __syncthreads();
        if (t < 32) {
            float ss = (t < 16) ? s_red[t] : 0.f;
            #pragma unroll
            for (int off = 8; off; off >>= 1)
                ss += __shfl_xor_sync(0xffffffffu, ss, off);
            if (t == 0) s_red[17] = ss;
        }
        __syncthreads();
        if (t < 128) out[t * G + g] = e / s_red[17];
    }
}

// ---------------------------------------------------------------------------
extern "C" void kernel_launch(void* const* d_in, const int* in_sizes, int n_in,
                              void* d_out, int out_size) {
    const float* ctrl       = (const float*)d_in[0];
    const float* shift_vec  = (const float*)d_in[1];
    const int*   gidx       = (const int*)  d_in[2];
    const float* ce_w1      = (const float*)d_in[3];
    const float* ce_b1      = (const float*)d_in[4];
    const float* ce_w2      = (const float*)d_in[5];
    const float* ce_b2      = (const float*)d_in[6];
    const float* gene_table = (const float*)d_in[7];
    const float* g_w1       = (const float*)d_in[8];
    const float* g_b1       = (const float*)d_in[9];
    const float* g_w2       = (const float*)d_in[10];
    const float* g_b2       = (const float*)d_in[11];
    const float* g_w3       = (const float*)d_in[12];
    float* out = (float*)d_out;

    const int G  = in_sizes[2];                 // number of selected genes
    const int Gc = in_sizes[0] / C_CELLS;       // ctrl width

    // raise dynamic smem limit for the main kernel (idempotent, non-stream op)
    static const size_t MAIN_SMEM = (size_t)(32768 + 128 + 256 * 5 + 128 + 32) * sizeof(float);
    cudaFuncSetAttribute(k_main, cudaFuncAttributeMaxDynamicSharedMemorySize, (int)MAIN_SMEM);

    k_hidden<<<C_CELLS, H_DIM, Gc * sizeof(float)>>>(ctrl, ce_w1, ce_b1, Gc);
    k_ceA<<<C_CELLS, H_DIM>>>(ce_w2, ce_b2, g_w1);
    k_B<<<G, H_DIM>>>(gene_table, shift_vec, gidx, g_w1, g_b1);
    k_main<<<G, 512, MAIN_SMEM>>>(ctrl, gidx, g_w1, g_w2, g_b2, g_w3, out, G, Gc);
}

// round 3
// speedup vs baseline: 6.6468x; 6.6468x over previous
#include <cuda_runtime.h>
#include <cuda_fp16.h>
#include <cstdint>
#include <math.h>

#define C_CELLS 128
#define H_DIM   256
#define CE_DIM  64
#define MAXG    2048
#define PADH    264      // padded row length (halves) -> 528B stride, conflict-free

// ---------------- device scratch (allocation-free rule) ----------------
__device__ float g_hidden[C_CELLS * H_DIM];
__device__ float g_Abuf[C_CELLS * H_DIM];            // ce @ W1[1:65]
__device__ float g_Bbuf[MAXG * H_DIM];               // gene-side layer1 bias
__device__ __align__(16) __half g_w2t[H_DIM * PADH]; // fp16 W2a^T [n][k], padded

__device__ __forceinline__ float eluf(float x) {
    return x > 0.f ? x : (__expf(x) - 1.f);
}
__device__ __forceinline__ uint32_t smem_to_u32(const void* p) {
    uint32_t a;
    asm("{ .reg .u64 t; cvta.to.shared.u64 t, %1; cvt.u32.u64 %0, t; }" : "=r"(a) : "l"(p));
    return a;
}
__device__ __forceinline__ void ldsm4(uint32_t* r, uint32_t addr) {
    asm volatile("ldmatrix.sync.aligned.m8n8.x4.shared.b16 {%0,%1,%2,%3}, [%4];"
                 : "=r"(r[0]), "=r"(r[1]), "=r"(r[2]), "=r"(r[3]) : "r"(addr));
}
__device__ __forceinline__ void mma16816(float* c, const uint32_t* a, const uint32_t* b) {
    asm volatile("mma.sync.aligned.m16n8k16.row.col.f32.f16.f16.f32 "
                 "{%0,%1,%2,%3}, {%4,%5,%6,%7}, {%8,%9}, {%0,%1,%2,%3};"
                 : "+f"(c[0]), "+f"(c[1]), "+f"(c[2]), "+f"(c[3])
                 : "r"(a[0]), "r"(a[1]), "r"(a[2]), "r"(a[3]), "r"(b[0]), "r"(b[1]));
}

// ---------------- SMEM layout (byte offsets into dynamic smem) ----------------
#define SM_H1    0                    // 128 x 264 fp16            (67584)
#define SM_W2T   67584                // 256 x 264 fp16            (135168)
#define SM_PART  202752               // 512 f32
#define SM_P1    204800               // 256 f32
#define SM_R     205824               // 256 f32
#define SM_W3A   206848               // 256 f32
#define SM_CTRL  207872               // 128 f32
#define SM_LOGIT 208384               // 128 f32
#define SM_RED   208896               // 32 f32
#define SM_TOTAL 209024

// ---------------------------------------------------------------------------
// K1: hidden[c,h] = elu(ctrl@ce_w1 + b1), tiled so ce_w1 is read ~8x not 128x.
// grid (8 hblk x 16 cellblk), 256 threads, smem = 8*G floats
// ---------------------------------------------------------------------------
__global__ void k_hidden(const float* __restrict__ ctrl, const float* __restrict__ w,
                         const float* __restrict__ b, int G) {
    extern __shared__ float s[];       // [8][G]
    const int t = threadIdx.x;
    const int hb = blockIdx.x, cb = blockIdx.y;
    for (int i = t; i < 8 * G; i += 256) {
        int cl = i / G, k = i - cl * G;
        s[cl * G + k] = ctrl[(cb * 8 + cl) * G + k];
    }
    __syncthreads();
    const int hl = t & 31, cl = t >> 5;          // 32 h x 8 cells
    const int h = hb * 32 + hl;
    const float* sc = s + cl * G;
    float a0 = 0.f, a1 = 0.f, a2 = 0.f, a3 = 0.f;
    int k = 0;
    for (; k + 3 < G; k += 4) {
        a0 = fmaf(sc[k+0], w[(k+0) * H_DIM + h], a0);
        a1 = fmaf(sc[k+1], w[(k+1) * H_DIM + h], a1);
        a2 = fmaf(sc[k+2], w[(k+2) * H_DIM + h], a2);
        a3 = fmaf(sc[k+3], w[(k+3) * H_DIM + h], a3);
    }
    for (; k < G; k++) a0 = fmaf(sc[k], w[k * H_DIM + h], a0);
    g_hidden[(cb * 8 + cl) * H_DIM + h] = eluf((a0 + a1) + (a2 + a3) + b[h]);
}

// ---------------------------------------------------------------------------
// K2: ce = hidden @ ce_w2 + ce_b2 ; A = ce @ W1[1:65]
// ---------------------------------------------------------------------------
__global__ void k_ceA(const float* __restrict__ ce_w2, const float* __restrict__ ce_b2,
                      const float* __restrict__ gw1) {
    __shared__ float s_hid[H_DIM];
    __shared__ float s_ce[CE_DIM];
    int c = blockIdx.x, t = threadIdx.x;
    s_hid[t] = g_hidden[c * H_DIM + t];
    __syncthreads();
    if (t < CE_DIM) {
        float a = ce_b2[t];
        #pragma unroll 4
        for (int k = 0; k < H_DIM; k++) a = fmaf(s_hid[k], ce_w2[k * CE_DIM + t], a);
        s_ce[t] = a;
    }
    __syncthreads();
    float a = 0.f;
    #pragma unroll
    for (int j = 0; j < CE_DIM; j++) a = fmaf(s_ce[j], gw1[(1 + j) * H_DIM + t], a);
    g_Abuf[c * H_DIM + t] = a;
}

// ---------------------------------------------------------------------------
// K3: B[g,:] = ge@W1[65:129] + shift*W1[129] + C*W1[130] + b1
// ---------------------------------------------------------------------------
__global__ void k_B(const float* __restrict__ gene_table, const float* __restrict__ shift_vec,
                    const int* __restrict__ gidx, const float* __restrict__ gw1,
                    const float* __restrict__ gb1) {
    __shared__ float s_ge[CE_DIM];
    __shared__ float s_shift;
    int g = blockIdx.x, t = threadIdx.x;
    int gi = gidx[g];
    if (t < CE_DIM) s_ge[t] = gene_table[gi * CE_DIM + t];
    if (t == 0) s_shift = shift_vec[gi];
    __syncthreads();
    float a = gb1[t] + s_shift * gw1[129 * H_DIM + t] + (float)C_CELLS * gw1[130 * H_DIM + t];
    #pragma unroll
    for (int j = 0; j < CE_DIM; j++) a = fmaf(s_ge[j], gw1[(65 + j) * H_DIM + t], a);
    g_Bbuf[g * H_DIM + t] = a;
}

// ---------------------------------------------------------------------------
// K_prep: fp16 image of W2a^T: g_w2t[n][k] = g_w2[k][n]
// ---------------------------------------------------------------------------
__global__ void k_prep(const float* __restrict__ gw2) {
    int n = blockIdx.x, h = threadIdx.x;
    g_w2t[n * PADH + h] = __float2half(gw2[h * H_DIM + n]);
}

// ---------------------------------------------------------------------------
// K_main: per-gene layer1(fp16 tile) -> HMMA GEMM -> elu.w3a -> softmax
// grid G x 512 threads
// ---------------------------------------------------------------------------
__global__ void __launch_bounds__(512, 1)
k_main(const float* __restrict__ ctrl, const int* __restrict__ gidx,
       const float* __restrict__ gw1, const float* __restrict__ gw2,
       const float* __restrict__ gb2, const float* __restrict__ gw3,
       float* __restrict__ out, int G, int Gc) {
    extern __shared__ char smem[];
    const uint32_t smem_u = smem_to_u32(smem);
    float* s_part  = (float*)(smem + SM_PART);
    float* s_p1    = (float*)(smem + SM_P1);
    float* s_r     = (float*)(smem + SM_R);
    float* s_w3a   = (float*)(smem + SM_W3A);
    float* s_ctrl  = (float*)(smem + SM_CTRL);
    float* s_logit = (float*)(smem + SM_LOGIT);
    float* s_red   = (float*)(smem + SM_RED);

    const int g = blockIdx.x;
    const int t = threadIdx.x;
    const int gi = gidx[g];

    if (t < 128) { s_ctrl[t] = ctrl[t * Gc + gi]; s_logit[t] = 0.f; }
    if (t < 256) s_w3a[t] = gw3[t];

    // copy W2a^T fp16 image into shared (135168 B = 8448 uint4)
    {
        const uint4* src = (const uint4*)g_w2t;
        uint4* dst = (uint4*)(smem + SM_W2T);
        #pragma unroll
        for (int i = t; i < 8448; i += 512) dst[i] = src[i];
    }
    __syncthreads();

    // ---- pass 1: h1 fp16 into SMEM A tile + fp32 partial column sums ----
    {
        const int h = t & 255, sub = t >> 8;     // sub 0: cells 0..63, sub 1: 64..127
        const float w10  = gw1[h];
        const float Brow = g_Bbuf[g * H_DIM + h];
        __half* a = (__half*)(smem + SM_H1);
        float sum = 0.f;
        #pragma unroll 4
        for (int cc = 0; cc < 64; cc++) {
            const int c = sub * 64 + cc;
            float v = fmaf(s_ctrl[c], w10, g_Abuf[c * H_DIM + h] + Brow);
            v = eluf(v);
            sum += v;
            a[c * PADH + h] = __float2half(v);
        }
        s_part[sub * 256 + h] = sum;
    }
    __syncthreads();

    // ---- HMMA GEMM: each warp owns m32 x n64 of x2 = h1 @ W2a ----
    const int w    = t >> 5, lane = t & 31;
    const int mrow = (w & 3) * 32;
    const int nbas = (w >> 2) * 64;
    const uint32_t aAddr = smem_u + SM_H1 +
        (uint32_t)(((mrow + (lane & 15)) * PADH + ((lane >> 4) << 3)) * 2);
    const uint32_t bAddr = smem_u + SM_W2T +
        (uint32_t)(((nbas + ((lane >> 4) << 3) + (lane & 7)) * PADH + (((lane >> 3) & 1) << 3)) * 2);

    float acc[2][8][4];
    #pragma unroll
    for (int mh = 0; mh < 2; mh++)
        #pragma unroll
        for (int j = 0; j < 8; j++)
            #pragma unroll
            for (int q = 0; q < 4; q++) acc[mh][j][q] = 0.f;

    #pragma unroll 2
    for (int ks = 0; ks < 16; ks++) {
        const uint32_t ko = (uint32_t)ks * 32;   // 16 halves * 2B
        uint32_t a[2][4], b[4][4];
        ldsm4(a[0], aAddr + ko);
        ldsm4(a[1], aAddr + ko + 16 * PADH * 2);
        #pragma unroll
        for (int j2 = 0; j2 < 4; j2++) ldsm4(b[j2], bAddr + ko + (uint32_t)j2 * (16 * PADH * 2));
        #pragma unroll
        for (int mh = 0; mh < 2; mh++)
            #pragma unroll
            for (int j = 0; j < 8; j++)
                mma16816(acc[mh][j], a[mh], &b[j >> 1][(j & 1) * 2]);
    }

    // ---- p1, r (needs GEMM done only for epilogue; s_part ready) ----
    __syncthreads();
    if (t < 256) s_p1[t] = (s_part[t] + s_part[256 + t]) * (1.f / (float)C_CELLS);
    __syncthreads();
    if (t < 256) {
        const float* w2b = gw2 + 256 * H_DIM;
        float a0 = gb2[t], a1 = 0.f, a2 = 0.f, a3 = 0.f;
        #pragma unroll 4
        for (int h = 0; h < H_DIM; h += 4) {
            a0 = fmaf(s_p1[h + 0], w2b[(h + 0) * H_DIM + t], a0);
            a1 = fmaf(s_p1[h + 1], w2b[(h + 1) * H_DIM + t], a1);
            a2 = fmaf(s_p1[h + 2], w2b[(h + 2) * H_DIM + t], a2);
            a3 = fmaf(s_p1[h + 3], w2b[(h + 3) * H_DIM + t], a3);
        }
        s_r[t] = (a0 + a1) + (a2 + a3);
    }
    __syncthreads();

    // ---- epilogue: fold elu(x2 + r[n]) * w3a[n] into per-cell logits ----
    {
        float p[4] = {0.f, 0.f, 0.f, 0.f};
        const int nb0 = nbas + ((lane & 3) << 1);
        #pragma unroll
        for (int mh = 0; mh < 2; mh++)
            #pragma unroll
            for (int j = 0; j < 8; j++) {
                const int n0 = nb0 + j * 8;
                const float w30 = s_w3a[n0], w31 = s_w3a[n0 + 1];
                const float rr0 = s_r[n0],  rr1 = s_r[n0 + 1];
                p[mh*2+0] = fmaf(eluf(acc[mh][j][0] + rr0), w30, p[mh*2+0]);
                p[mh*2+0] = fmaf(eluf(acc[mh][j][1] + rr1), w31, p[mh*2+0]);
                p[mh*2+1] = fmaf(eluf(acc[mh][j][2] + rr0), w30, p[mh*2+1]);
                p[mh*2+1] = fmaf(eluf(acc[mh][j][3] + rr1), w31, p[mh*2+1]);
            }
        #pragma unroll
        for (int i = 0; i < 4; i++) {
            p[i] += __shfl_xor_sync(0xffffffffu, p[i], 1);
            p[i] += __shfl_xor_sync(0xffffffffu, p[i], 2);
        }
        if ((lane & 3) == 0) {
            #pragma unroll
            for (int i = 0; i < 4; i++)
                atomicAdd(&s_logit[mrow + (i >> 1) * 16 + (i & 1) * 8 + (lane >> 2)], p[i]);
        }
    }
    __syncthreads();

    // ---- softmax over 128 cells (per-gene additive constants cancel) ----
    {
        const int wid = t >> 5;
        float l = (t < 128) ? s_logit[t] : -1e30f;
        float m = l;
        #pragma unroll
        for (int off = 16; off; off >>= 1) m = fmaxf(m, __shfl_xor_sync(0xffffffffu, m, off));
        if (lane == 0) s_red[wid] = m;
        __syncthreads();
        if (t < 32) {
            float mm = (t < 16) ? s_red[t] : -1e30f;
            #pragma unroll
            for (int off = 8; off; off >>= 1) mm = fmaxf(mm, __shfl_xor_sync(0xffffffffu, mm, off));
            if (t == 0) s_red[16] = mm;
        }
        __syncthreads();
        const float M = s_red[16];
        float e = (t < 128) ? __expf(l - M) : 0.f;
        float s = e;
        #pragma unroll
        for (int off = 16; off; off >>= 1) s += __shfl_xor_sync(0xffffffffu, s, off);
        if (lane == 0) s_red[wid] = s;
        __syncthreads();
        if (t < 32) {
            float ss = (t < 16) ? s_red[t] : 0.f;
            #pragma unroll
            for (int off = 8; off; off >>= 1) ss += __shfl_xor_sync(0xffffffffu, ss, off);
            if (t == 0) s_red[17] = ss;
        }
        __syncthreads();
        if (t < 128) out[t * G + g] = e / s_red[17];
    }
}

// ---------------------------------------------------------------------------
extern "C" void kernel_launch(void* const* d_in, const int* in_sizes, int n_in,
                              void* d_out, int out_size) {
    const float* ctrl       = (const float*)d_in[0];
    const float* shift_vec  = (const float*)d_in[1];
    const int*   gidx       = (const int*)  d_in[2];
    const float* ce_w1      = (const float*)d_in[3];
    const float* ce_b1      = (const float*)d_in[4];
    const float* ce_w2      = (const float*)d_in[5];
    const float* ce_b2      = (const float*)d_in[6];
    const float* gene_table = (const float*)d_in[7];
    const float* g_w1       = (const float*)d_in[8];
    const float* g_b1       = (const float*)d_in[9];
    const float* g_w2       = (const float*)d_in[10];
    const float* g_b2       = (const float*)d_in[11];
    const float* g_w3       = (const float*)d_in[12];
    float* out = (float*)d_out;

    const int G  = in_sizes[2];
    const int Gc = in_sizes[0] / C_CELLS;

    cudaFuncSetAttribute(k_main, cudaFuncAttributeMaxDynamicSharedMemorySize, SM_TOTAL);
    cudaFuncSetAttribute(k_hidden, cudaFuncAttributeMaxDynamicSharedMemorySize, 8 * Gc * (int)sizeof(float));

    k_hidden<<<dim3(8, 16), 256, 8 * Gc * sizeof(float)>>>(ctrl, ce_w1, ce_b1, Gc);
    k_ceA<<<C_CELLS, H_DIM>>>(ce_w2, ce_b2, g_w1);
    k_B<<<G, H_DIM>>>(gene_table, shift_vec, gidx, g_w1, g_b1);
    k_prep<<<H_DIM, H_DIM>>>(g_w2);
    k_main<<<G, 512, SM_TOTAL>>>(ctrl, gidx, g_w1, g_w2, g_b2, g_w3, out, G, Gc);
}